// round 5
// baseline (speedup 1.0000x reference)
#include <cuda_runtime.h>
#include <cfloat>
#include <cstdint>

// ---------------- constants ----------------
#define BB    32
#define TA    128
#define TB    1024
#define DIN   1280
#define DEMB  512
#define MPEP  (BB*TA)     // 4096
#define MREC  (BB*TB)     // 32768
#define SPAD  136         // u32 per smem k-row (conflict-free fragment loads)

// ---------------- scratch (static device globals; no allocation) ------------
__device__ float g_E[MREC * DEMB];
__device__ float g_H[MREC * DEMB];
__device__ float g_hA[MPEP * DEMB];
__device__ float g_hB[MREC * DEMB];
__device__ float g_sAp[BB * BB * 8 * TA];
__device__ float g_sB[BB * BB * TB];

// ---------------- helpers ----------------
__device__ __forceinline__ void atomicMaxF(float* addr, float val) {
    if (val >= 0.f) atomicMax((int*)addr, __float_as_int(val));
    else            atomicMin((unsigned int*)addr, __float_as_uint(val));
}

__device__ __forceinline__ uint32_t f2tf32(float f) {
    uint32_t u;
    asm("cvt.rna.tf32.f32 %0, %1;" : "=r"(u) : "f"(f));
    return u;
}

__device__ __forceinline__ void mma_tf32(float c[4],
    uint32_t a0, uint32_t a1, uint32_t a2, uint32_t a3,
    uint32_t b0, uint32_t b1)
{
    asm volatile(
        "mma.sync.aligned.m16n8k8.row.col.f32.tf32.tf32.f32 "
        "{%0,%1,%2,%3}, {%4,%5,%6,%7}, {%8,%9}, {%0,%1,%2,%3};"
        : "+f"(c[0]), "+f"(c[1]), "+f"(c[2]), "+f"(c[3])
        : "r"(a0), "r"(a1), "r"(a2), "r"(a3), "r"(b0), "r"(b1));
}

__device__ __forceinline__ float blockReduceSum256(float v, float* sbuf) {
    int tid = threadIdx.x;
    __syncthreads();
    sbuf[tid] = v;
    __syncthreads();
    #pragma unroll
    for (int s = 128; s > 0; s >>= 1) {
        if (tid < s) sbuf[tid] += sbuf[tid + s];
        __syncthreads();
    }
    float r = sbuf[0];
    __syncthreads();
    return r;
}

// =============================================================================
// Tensor-core GEMM (encoders): C[M,N] = A[M,K] @ B[K,N] + bias, optional ReLU.
// A row-major (transposed into k-major smem), B row-major k-major (direct copy).
// 128x128 block tile, Ktile=16, 256 threads = 8 warps (2m x 4n), warp 64x32.
// mma.sync m16n8k8 tf32, fp32 accumulate, double-buffered smem.
// Requires M%128==0, N%128==0, K%16==0.
// =============================================================================
template<bool RELU>
__global__ __launch_bounds__(256)
void gemm_tc(const float* __restrict__ A, const float* __restrict__ B,
             const float* __restrict__ bias, float* __restrict__ C,
             int M, int N, int K)
{
    __shared__ uint32_t As[2][16][SPAD];
    __shared__ uint32_t Bs[2][16][SPAD];

    const int tid  = threadIdx.x;
    const int bx   = blockIdx.x;
    const int by   = blockIdx.y;
    const int wid  = tid >> 5;
    const int lane = tid & 31;
    const int g    = lane >> 2;   // group id 0..7
    const int tg   = lane & 3;    // thread in group 0..3
    const int m_base = (wid >> 2) * 64;   // 0 / 64
    const int n_base = (wid & 3) * 32;    // 0..96

    float acc[4][4][4];
    #pragma unroll
    for (int mt = 0; mt < 4; mt++)
        #pragma unroll
        for (int nt = 0; nt < 4; nt++)
            #pragma unroll
            for (int e = 0; e < 4; e++) acc[mt][nt][e] = 0.f;

    // A loader (transposing): row ar, k-offset ah + j*8
    const int ar = tid >> 1;          // 0..127
    const int ah = (tid & 1) * 4;     // 0 / 4
    const float* Ag = A + (size_t)(by * 128 + ar) * K + ah;
    // B loader (direct): k-row bk + j*8, col chunk bn4
    const int bk  = tid >> 5;         // 0..7
    const int bn4 = (tid & 31) * 4;   // 0..124
    const float* Bg = B + (size_t)bk * N + bx * 128 + bn4;

    float a_reg[2][4], b_reg[2][4];

    const int KT = K / 16;

    // ---- prologue: load tile 0 ----
    #pragma unroll
    for (int j = 0; j < 2; j++) {
        *(float4*)a_reg[j] = *(const float4*)(Ag + j * 8);
        *(float4*)b_reg[j] = *(const float4*)(Bg + (size_t)(j * 8) * N);
    }
    #pragma unroll
    for (int j = 0; j < 2; j++) {
        #pragma unroll
        for (int i = 0; i < 4; i++)
            As[0][ah + j * 8 + i][ar] = f2tf32(a_reg[j][i]);
        uint4 bv;
        bv.x = f2tf32(b_reg[j][0]); bv.y = f2tf32(b_reg[j][1]);
        bv.z = f2tf32(b_reg[j][2]); bv.w = f2tf32(b_reg[j][3]);
        *(uint4*)&Bs[0][bk + j * 8][bn4] = bv;
    }
    __syncthreads();

    for (int kt = 0; kt < KT; kt++) {
        const int buf = kt & 1;
        if (kt + 1 < KT) {
            const int k0 = (kt + 1) * 16;
            #pragma unroll
            for (int j = 0; j < 2; j++) {
                *(float4*)a_reg[j] = *(const float4*)(Ag + k0 + j * 8);
                *(float4*)b_reg[j] = *(const float4*)(Bg + (size_t)(k0 + j * 8) * N);
            }
        }
        // ---- math on buf ----
        #pragma unroll
        for (int ks = 0; ks < 16; ks += 8) {
            uint32_t af[4][4], bf[4][2];
            #pragma unroll
            for (int mt = 0; mt < 4; mt++) {
                int m0 = m_base + mt * 16;
                af[mt][0] = As[buf][ks + tg][m0 + g];
                af[mt][1] = As[buf][ks + tg][m0 + g + 8];
                af[mt][2] = As[buf][ks + tg + 4][m0 + g];
                af[mt][3] = As[buf][ks + tg + 4][m0 + g + 8];
            }
            #pragma unroll
            for (int nt = 0; nt < 4; nt++) {
                int n0 = n_base + nt * 8;
                bf[nt][0] = Bs[buf][ks + tg][n0 + g];
                bf[nt][1] = Bs[buf][ks + tg + 4][n0 + g];
            }
            #pragma unroll
            for (int mt = 0; mt < 4; mt++)
                #pragma unroll
                for (int nt = 0; nt < 4; nt++)
                    mma_tf32(acc[mt][nt], af[mt][0], af[mt][1], af[mt][2], af[mt][3],
                             bf[nt][0], bf[nt][1]);
        }
        if (kt + 1 < KT) {
            const int nb = buf ^ 1;
            #pragma unroll
            for (int j = 0; j < 2; j++) {
                #pragma unroll
                for (int i = 0; i < 4; i++)
                    As[nb][ah + j * 8 + i][ar] = f2tf32(a_reg[j][i]);
                uint4 bv;
                bv.x = f2tf32(b_reg[j][0]); bv.y = f2tf32(b_reg[j][1]);
                bv.z = f2tf32(b_reg[j][2]); bv.w = f2tf32(b_reg[j][3]);
                *(uint4*)&Bs[nb][bk + j * 8][bn4] = bv;
            }
            __syncthreads();
        }
    }

    // ---- epilogue: bias + optional ReLU ----
    #pragma unroll
    for (int mt = 0; mt < 4; mt++) {
        const int row0 = by * 128 + m_base + mt * 16 + g;
        #pragma unroll
        for (int nt = 0; nt < 4; nt++) {
            const int col = bx * 128 + n_base + nt * 8 + tg * 2;
            const float b0 = bias[col], b1 = bias[col + 1];
            float v0 = acc[mt][nt][0] + b0;
            float v1 = acc[mt][nt][1] + b1;
            float v2 = acc[mt][nt][2] + b0;
            float v3 = acc[mt][nt][3] + b1;
            if (RELU) {
                v0 = fmaxf(v0, 0.f); v1 = fmaxf(v1, 0.f);
                v2 = fmaxf(v2, 0.f); v3 = fmaxf(v3, 0.f);
            }
            *(float2*)&C[(size_t)row0 * N + col]       = make_float2(v0, v1);
            *(float2*)&C[(size_t)(row0 + 8) * N + col] = make_float2(v2, v3);
        }
    }
}

// =============================================================================
// Tensor-core sim GEMM + fused masked max reductions.
// grid (stile=8, b=32, a=32). Tile [128 tA x 128 tb] = hA_tile @ hB_tile^T / T.
// Both operands row-major [rows, DEMB] -> transposed into k-major smem.
// =============================================================================
__global__ __launch_bounds__(256)
void sim_tc(const float* __restrict__ hA, const float* __restrict__ hB,
            const int* __restrict__ mA, const int* __restrict__ mB,
            const float* __restrict__ temp,
            float* __restrict__ sAp, float* __restrict__ sB)
{
    __shared__ uint32_t As[2][16][SPAD];
    __shared__ uint32_t Bs[2][16][SPAD];
    __shared__ float rowmax[128];
    __shared__ float colmax[128];
    __shared__ int   smA[128];
    __shared__ int   smB[128];

    const int stile = blockIdx.x;
    const int b     = blockIdx.y;
    const int a     = blockIdx.z;
    const int tid  = threadIdx.x;
    const int wid  = tid >> 5;
    const int lane = tid & 31;
    const int g    = lane >> 2;
    const int tg   = lane & 3;
    const int m_base = (wid >> 2) * 64;
    const int n_base = (wid & 3) * 32;

    if (tid < 128) {
        rowmax[tid] = -FLT_MAX;
        colmax[tid] = -FLT_MAX;
        smA[tid] = mA[a * TA + tid];
        smB[tid] = mB[b * TB + stile * 128 + tid];
    }

    float acc[4][4][4];
    #pragma unroll
    for (int mt = 0; mt < 4; mt++)
        #pragma unroll
        for (int nt = 0; nt < 4; nt++)
            #pragma unroll
            for (int e = 0; e < 4; e++) acc[mt][nt][e] = 0.f;

    // both loaders transposing, 128 rows x 16 k
    const int ar = tid >> 1;
    const int ah = (tid & 1) * 4;
    const float* Ag = hA + (size_t)(a * TA + ar) * DEMB + ah;
    const float* Bg = hB + (size_t)(b * TB + stile * 128 + ar) * DEMB + ah;

    float a_reg[2][4], b_reg[2][4];
    const int KT = DEMB / 16;   // 32

    #pragma unroll
    for (int j = 0; j < 2; j++) {
        *(float4*)a_reg[j] = *(const float4*)(Ag + j * 8);
        *(float4*)b_reg[j] = *(const float4*)(Bg + j * 8);
    }
    #pragma unroll
    for (int j = 0; j < 2; j++)
        #pragma unroll
        for (int i = 0; i < 4; i++) {
            As[0][ah + j * 8 + i][ar] = f2tf32(a_reg[j][i]);
            Bs[0][ah + j * 8 + i][ar] = f2tf32(b_reg[j][i]);
        }
    __syncthreads();

    for (int kt = 0; kt < KT; kt++) {
        const int buf = kt & 1;
        if (kt + 1 < KT) {
            const int k0 = (kt + 1) * 16;
            #pragma unroll
            for (int j = 0; j < 2; j++) {
                *(float4*)a_reg[j] = *(const float4*)(Ag + k0 + j * 8);
                *(float4*)b_reg[j] = *(const float4*)(Bg + k0 + j * 8);
            }
        }
        #pragma unroll
        for (int ks = 0; ks < 16; ks += 8) {
            uint32_t af[4][4], bf[4][2];
            #pragma unroll
            for (int mt = 0; mt < 4; mt++) {
                int m0 = m_base + mt * 16;
                af[mt][0] = As[buf][ks + tg][m0 + g];
                af[mt][1] = As[buf][ks + tg][m0 + g + 8];
                af[mt][2] = As[buf][ks + tg + 4][m0 + g];
                af[mt][3] = As[buf][ks + tg + 4][m0 + g + 8];
            }
            #pragma unroll
            for (int nt = 0; nt < 4; nt++) {
                int n0 = n_base + nt * 8;
                bf[nt][0] = Bs[buf][ks + tg][n0 + g];
                bf[nt][1] = Bs[buf][ks + tg + 4][n0 + g];
            }
            #pragma unroll
            for (int mt = 0; mt < 4; mt++)
                #pragma unroll
                for (int nt = 0; nt < 4; nt++)
                    mma_tf32(acc[mt][nt], af[mt][0], af[mt][1], af[mt][2], af[mt][3],
                             bf[nt][0], bf[nt][1]);
        }
        if (kt + 1 < KT) {
            const int nb = buf ^ 1;
            #pragma unroll
            for (int j = 0; j < 2; j++)
                #pragma unroll
                for (int i = 0; i < 4; i++) {
                    As[nb][ah + j * 8 + i][ar] = f2tf32(a_reg[j][i]);
                    Bs[nb][ah + j * 8 + i][ar] = f2tf32(b_reg[j][i]);
                }
            __syncthreads();
        }
    }

    // ---- fused masked max epilogue ----
    const float invT = 1.0f / temp[0];
    float rowm[4][2];   // [mt][half]
    float colm[4][2];   // [nt][pair]
    #pragma unroll
    for (int i = 0; i < 4; i++) {
        rowm[i][0] = rowm[i][1] = -FLT_MAX;
        colm[i][0] = colm[i][1] = -FLT_MAX;
    }
    #pragma unroll
    for (int mt = 0; mt < 4; mt++) {
        const int rl0 = m_base + mt * 16 + g;
        const int ma0 = smA[rl0];
        const int ma1 = smA[rl0 + 8];
        #pragma unroll
        for (int nt = 0; nt < 4; nt++) {
            const int cl0 = n_base + nt * 8 + tg * 2;
            const int mb0 = smB[cl0];
            const int mb1 = smB[cl0 + 1];
            float v00 = (ma0 && mb0) ? acc[mt][nt][0] * invT : -FLT_MAX;
            float v01 = (ma0 && mb1) ? acc[mt][nt][1] * invT : -FLT_MAX;
            float v10 = (ma1 && mb0) ? acc[mt][nt][2] * invT : -FLT_MAX;
            float v11 = (ma1 && mb1) ? acc[mt][nt][3] * invT : -FLT_MAX;
            rowm[mt][0] = fmaxf(rowm[mt][0], fmaxf(v00, v01));
            rowm[mt][1] = fmaxf(rowm[mt][1], fmaxf(v10, v11));
            colm[nt][0] = fmaxf(colm[nt][0], fmaxf(v00, v10));
            colm[nt][1] = fmaxf(colm[nt][1], fmaxf(v01, v11));
        }
    }
    #pragma unroll
    for (int mt = 0; mt < 4; mt++) {
        atomicMaxF(&rowmax[m_base + mt * 16 + g],     rowm[mt][0]);
        atomicMaxF(&rowmax[m_base + mt * 16 + g + 8], rowm[mt][1]);
    }
    #pragma unroll
    for (int nt = 0; nt < 4; nt++) {
        atomicMaxF(&colmax[n_base + nt * 8 + tg * 2],     colm[nt][0]);
        atomicMaxF(&colmax[n_base + nt * 8 + tg * 2 + 1], colm[nt][1]);
    }
    __syncthreads();

    if (tid < 128) {
        const int ab = a * BB + b;
        sAp[((size_t)ab * 8 + stile) * TA + tid] = rowmax[tid];
        sB[(size_t)ab * TB + stile * 128 + tid]  = colmax[tid];
    }
}

// ---------------- LayerNorm over last dim (512), one block per row ----------
__global__ __launch_bounds__(256)
void ln_kernel(float* __restrict__ H, const float* __restrict__ g,
               const float* __restrict__ b)
{
    __shared__ float sbuf[256];
    const int row = blockIdx.x;
    const int tid = threadIdx.x;
    float* h = H + (size_t)row * DEMB;
    float x0 = h[tid], x1 = h[tid + 256];
    float mu = blockReduceSum256(x0 + x1, sbuf) * (1.f / DEMB);
    float d0 = x0 - mu, d1 = x1 - mu;
    float var = blockReduceSum256(d0 * d0 + d1 * d1, sbuf) * (1.f / DEMB);
    float r = rsqrtf(var + 1e-5f);
    h[tid]       = d0 * r * g[tid]       + b[tid];
    h[tid + 256] = d1 * r * g[tid + 256] + b[tid + 256];
}

// ---------------- L2 row-normalize, one block per row -----------------------
__global__ __launch_bounds__(256)
void rownorm_kernel(float* __restrict__ X)
{
    __shared__ float sbuf[256];
    const int row = blockIdx.x;
    const int tid = threadIdx.x;
    float* x = X + (size_t)row * DEMB;
    float x0 = x[tid], x1 = x[tid + 256];
    float s = blockReduceSum256(x0 * x0 + x1 * x1, sbuf);
    float inv = rsqrtf(s);
    x[tid]       = x0 * inv;
    x[tid + 256] = x1 * inv;
}

// ---------------- finalize: masked means -> out [2,32,32] -------------------
__global__ __launch_bounds__(256)
void finalize_kernel(const float* __restrict__ sAp, const float* __restrict__ sB,
                     const int* __restrict__ mA, const int* __restrict__ mB,
                     float* __restrict__ out)
{
    __shared__ float sbuf[256];
    const int b = blockIdx.x;
    const int a = blockIdx.y;
    const int tid = threadIdx.x;
    const int ab = a * BB + b;

    float vA = 0.f, cA = 0.f;
    if (tid < TA) {
        const float* p = sAp + (size_t)ab * 8 * TA + tid;
        float m = p[0];
        #pragma unroll
        for (int t = 1; t < 8; t++) m = fmaxf(m, p[t * TA]);
        int msk = mA[a * TA + tid];
        vA = msk ? m : 0.f;
        cA = (float)msk;
    }
    float sumA = blockReduceSum256(vA, sbuf);
    float cntA = blockReduceSum256(cA, sbuf);

    float vB = 0.f, cB = 0.f;
    #pragma unroll
    for (int j = 0; j < 4; j++) {
        int s = tid + j * 256;
        int msk = mB[b * TB + s];
        float v = sB[(size_t)ab * TB + s];
        vB += msk ? v : 0.f;
        cB += (float)msk;
    }
    float sumB = blockReduceSum256(vB, sbuf);
    float cntB = blockReduceSum256(cB, sbuf);

    if (tid == 0) {
        out[ab]           = sumA / fmaxf(cntA, 1e-6f);
        out[BB * BB + ab] = sumB / fmaxf(cntB, 1e-6f);
    }
}

// ---------------- launch ----------------
extern "C" void kernel_launch(void* const* d_in, const int* in_sizes, int n_in,
                              void* d_out, int out_size)
{
    const float* pep_esm  = (const float*)d_in[0];
    const float* rec_esm  = (const float*)d_in[1];
    const int*   pep_mask = (const int*)d_in[2];
    const int*   rec_mask = (const int*)d_in[3];
    const float* temp     = (const float*)d_in[4];
    const float* pep_pw  = (const float*)d_in[5];
    const float* pep_pb  = (const float*)d_in[6];
    const float* pep_f1w = (const float*)d_in[7];
    const float* pep_f1b = (const float*)d_in[8];
    const float* pep_lng = (const float*)d_in[9];
    const float* pep_lnb = (const float*)d_in[10];
    const float* pep_f2w = (const float*)d_in[11];
    const float* pep_f2b = (const float*)d_in[12];
    const float* rec_pw  = (const float*)d_in[13];
    const float* rec_pb  = (const float*)d_in[14];
    const float* rec_f1w = (const float*)d_in[15];
    const float* rec_f1b = (const float*)d_in[16];
    const float* rec_lng = (const float*)d_in[17];
    const float* rec_lnb = (const float*)d_in[18];
    const float* rec_f2w = (const float*)d_in[19];
    const float* rec_f2b = (const float*)d_in[20];

    float *pE, *pH, *phA, *phB, *psAp, *psB;
    cudaGetSymbolAddress((void**)&pE,   g_E);
    cudaGetSymbolAddress((void**)&pH,   g_H);
    cudaGetSymbolAddress((void**)&phA,  g_hA);
    cudaGetSymbolAddress((void**)&phB,  g_hB);
    cudaGetSymbolAddress((void**)&psAp, g_sAp);
    cudaGetSymbolAddress((void**)&psB,  g_sB);

    // ---- pep encoder: M=4096 ----
    gemm_tc<false><<<dim3(DEMB / 128, MPEP / 128), 256>>>(pep_esm, pep_pw, pep_pb, pE, MPEP, DEMB, DIN);
    gemm_tc<true ><<<dim3(DEMB / 128, MPEP / 128), 256>>>(pE, pep_f1w, pep_f1b, pH, MPEP, DEMB, DEMB);
    ln_kernel<<<MPEP, 256>>>(pH, pep_lng, pep_lnb);
    gemm_tc<false><<<dim3(DEMB / 128, MPEP / 128), 256>>>(pH, pep_f2w, pep_f2b, phA, MPEP, DEMB, DEMB);
    rownorm_kernel<<<MPEP, 256>>>(phA);

    // ---- rec encoder: M=32768 ----
    gemm_tc<false><<<dim3(DEMB / 128, MREC / 128), 256>>>(rec_esm, rec_pw, rec_pb, pE, MREC, DEMB, DIN);
    gemm_tc<true ><<<dim3(DEMB / 128, MREC / 128), 256>>>(pE, rec_f1w, rec_f1b, pH, MREC, DEMB, DEMB);
    ln_kernel<<<MREC, 256>>>(pH, rec_lng, rec_lnb);
    gemm_tc<false><<<dim3(DEMB / 128, MREC / 128), 256>>>(pH, rec_f2w, rec_f2b, phB, MREC, DEMB, DEMB);
    rownorm_kernel<<<MREC, 256>>>(phB);

    // ---- fused sim + masked max ----
    sim_tc<<<dim3(TB / 128, BB, BB), 256>>>(phA, phB, pep_mask, rec_mask, temp, psAp, psB);

    // ---- masked means ----
    finalize_kernel<<<dim3(BB, BB), 256>>>(psAp, psB, pep_mask, rec_mask, (float*)d_out);
}

// round 11
// speedup vs baseline: 1.6951x; 1.6951x over previous
#include <cuda_runtime.h>
#include <cuda_bf16.h>
#include <cfloat>
#include <cstdint>

// ---------------- constants ----------------
#define BB    32
#define TA    128
#define TB    1024
#define DIN   1280
#define DEMB  512
#define MPEP  (BB*TA)     // 4096
#define MREC  (BB*TB)     // 32768
#define SPAD  136         // u32 per smem pair-row (conflict-free fragment loads)

// ---------------- scratch (static device globals; no allocation) ------------
__device__ float g_E[MREC * DEMB];               // fp32 intermediate (64 MB)
__device__ float g_H[MREC * DEMB];               // fp32 intermediate (64 MB)
__device__ __nv_bfloat16 g_hAb[MPEP * DEMB];     // bf16 normalized pep (4 MB)
__device__ __nv_bfloat16 g_hBb[MREC * DEMB];     // bf16 normalized rec (32 MB)
__device__ float g_sAp[BB * BB * 8 * TA];
__device__ float g_sB[BB * BB * TB];

// ---------------- helpers ----------------
__device__ __forceinline__ void atomicMaxF(float* addr, float val) {
    if (val >= 0.f) atomicMax((int*)addr, __float_as_int(val));
    else            atomicMin((unsigned int*)addr, __float_as_uint(val));
}

__device__ __forceinline__ uint32_t pack_bf16(float lo, float hi) {
    __nv_bfloat162 h = __floats2bfloat162_rn(lo, hi);
    return *(uint32_t*)&h;
}

// m16n8k16 bf16 MMA, fp32 accumulate.
__device__ __forceinline__ void mma_bf16(float c[4],
    uint32_t a0, uint32_t a1, uint32_t a2, uint32_t a3,
    uint32_t b0, uint32_t b1)
{
    asm volatile(
        "mma.sync.aligned.m16n8k16.row.col.f32.bf16.bf16.f32 "
        "{%0,%1,%2,%3}, {%4,%5,%6,%7}, {%8,%9}, {%0,%1,%2,%3};"
        : "+f"(c[0]), "+f"(c[1]), "+f"(c[2]), "+f"(c[3])
        : "r"(a0), "r"(a1), "r"(a2), "r"(a3), "r"(b0), "r"(b1));
}

__device__ __forceinline__ float blockReduceSum256(float v, float* sbuf) {
    int tid = threadIdx.x;
    __syncthreads();
    sbuf[tid] = v;
    __syncthreads();
    #pragma unroll
    for (int s = 128; s > 0; s >>= 1) {
        if (tid < s) sbuf[tid] += sbuf[tid + s];
        __syncthreads();
    }
    float r = sbuf[0];
    __syncthreads();
    return r;
}

// =============================================================================
// bf16 tensor-core GEMM (encoders): C[M,N] = A[M,K] @ B[K,N] + bias, opt ReLU.
// fp32 global operands converted to bf16 pairs at smem-store time.
// Smem holds bf16x2 per u32: As[pair k][m], Bs[pair k][n]. Ktile=16 (8 pairs).
// 256 threads = 8 warps (2m x 4n), warp tile 64x32. Double-buffered, 1 sync/iter.
// =============================================================================
template<bool RELU>
__global__ __launch_bounds__(256)
void gemm_bf(const float* __restrict__ A, const float* __restrict__ B,
             const float* __restrict__ bias, float* __restrict__ C,
             int M, int N, int K)
{
    __shared__ uint32_t As[2][8][SPAD];
    __shared__ uint32_t Bs[2][8][SPAD];

    const int tid  = threadIdx.x;
    const int bx   = blockIdx.x;
    const int by   = blockIdx.y;
    const int wid  = tid >> 5;
    const int lane = tid & 31;
    const int g    = lane >> 2;
    const int tg   = lane & 3;
    const int m_base = (wid >> 2) * 64;
    const int n_base = (wid & 3) * 32;

    float acc[4][4][4];
    #pragma unroll
    for (int mt = 0; mt < 4; mt++)
        #pragma unroll
        for (int nt = 0; nt < 4; nt++)
            #pragma unroll
            for (int e = 0; e < 4; e++) acc[mt][nt][e] = 0.f;

    // A loader: row ar, k halves ah..ah+7 (pair rows ap..ap+3)
    const int ar = tid >> 1;            // 0..127
    const int ah = (tid & 1) * 8;       // 0 / 8
    const int ap = (tid & 1) * 4;       // pair row base 0 / 4
    const float* Ag = A + (size_t)(by * 128 + ar) * K + ah;
    // B loader: pair row pk (k rows 2pk, 2pk+1), 4 cols
    const int pk  = tid >> 5;           // 0..7
    const int bn4 = (tid & 31) * 4;     // 0..124
    const float* Bg = B + (size_t)(2 * pk) * N + bx * 128 + bn4;

    float a0[4], a1[4], blo[4], bhi[4];
    const int KT = K / 16;

    // ---- prologue: tile 0 ----
    *(float4*)a0  = *(const float4*)(Ag);
    *(float4*)a1  = *(const float4*)(Ag + 4);
    *(float4*)blo = *(const float4*)(Bg);
    *(float4*)bhi = *(const float4*)(Bg + N);
    {
        As[0][ap + 0][ar] = pack_bf16(a0[0], a0[1]);
        As[0][ap + 1][ar] = pack_bf16(a0[2], a0[3]);
        As[0][ap + 2][ar] = pack_bf16(a1[0], a1[1]);
        As[0][ap + 3][ar] = pack_bf16(a1[2], a1[3]);
        uint4 bv;
        bv.x = pack_bf16(blo[0], bhi[0]);
        bv.y = pack_bf16(blo[1], bhi[1]);
        bv.z = pack_bf16(blo[2], bhi[2]);
        bv.w = pack_bf16(blo[3], bhi[3]);
        *(uint4*)&Bs[0][pk][bn4] = bv;
    }
    __syncthreads();

    for (int kt = 0; kt < KT; kt++) {
        const int buf = kt & 1;
        if (kt + 1 < KT) {
            const int k0 = (kt + 1) * 16;
            *(float4*)a0  = *(const float4*)(Ag + k0);
            *(float4*)a1  = *(const float4*)(Ag + k0 + 4);
            *(float4*)blo = *(const float4*)(Bg + (size_t)k0 * N);
            *(float4*)bhi = *(const float4*)(Bg + (size_t)(k0 + 1) * N);
        }
        // ---- math: one m16n8k16 sweep covers the whole 16-k tile ----
        {
            uint32_t af[4][4], bf[4][2];
            #pragma unroll
            for (int mt = 0; mt < 4; mt++) {
                int m0 = m_base + mt * 16;
                af[mt][0] = As[buf][tg][m0 + g];
                af[mt][1] = As[buf][tg][m0 + g + 8];
                af[mt][2] = As[buf][tg + 4][m0 + g];
                af[mt][3] = As[buf][tg + 4][m0 + g + 8];
            }
            #pragma unroll
            for (int nt = 0; nt < 4; nt++) {
                int n0 = n_base + nt * 8;
                bf[nt][0] = Bs[buf][tg][n0 + g];
                bf[nt][1] = Bs[buf][tg + 4][n0 + g];
            }
            #pragma unroll
            for (int mt = 0; mt < 4; mt++)
                #pragma unroll
                for (int nt = 0; nt < 4; nt++)
                    mma_bf16(acc[mt][nt], af[mt][0], af[mt][1], af[mt][2], af[mt][3],
                             bf[nt][0], bf[nt][1]);
        }
        if (kt + 1 < KT) {
            const int nb = buf ^ 1;
            As[nb][ap + 0][ar] = pack_bf16(a0[0], a0[1]);
            As[nb][ap + 1][ar] = pack_bf16(a0[2], a0[3]);
            As[nb][ap + 2][ar] = pack_bf16(a1[0], a1[1]);
            As[nb][ap + 3][ar] = pack_bf16(a1[2], a1[3]);
            uint4 bv;
            bv.x = pack_bf16(blo[0], bhi[0]);
            bv.y = pack_bf16(blo[1], bhi[1]);
            bv.z = pack_bf16(blo[2], bhi[2]);
            bv.w = pack_bf16(blo[3], bhi[3]);
            *(uint4*)&Bs[nb][pk][bn4] = bv;
            __syncthreads();
        }
    }

    // ---- epilogue: bias + optional ReLU ----
    #pragma unroll
    for (int mt = 0; mt < 4; mt++) {
        const int row0 = by * 128 + m_base + mt * 16 + g;
        #pragma unroll
        for (int nt = 0; nt < 4; nt++) {
            const int col = bx * 128 + n_base + nt * 8 + tg * 2;
            const float b0 = bias[col], b1 = bias[col + 1];
            float v0 = acc[mt][nt][0] + b0;
            float v1 = acc[mt][nt][1] + b1;
            float v2 = acc[mt][nt][2] + b0;
            float v3 = acc[mt][nt][3] + b1;
            if (RELU) {
                v0 = fmaxf(v0, 0.f); v1 = fmaxf(v1, 0.f);
                v2 = fmaxf(v2, 0.f); v3 = fmaxf(v3, 0.f);
            }
            *(float2*)&C[(size_t)row0 * N + col]       = make_float2(v0, v1);
            *(float2*)&C[(size_t)(row0 + 8) * N + col] = make_float2(v2, v3);
        }
    }
}

// =============================================================================
// bf16 sim GEMM + fused masked max. Operands already bf16 row-major [rows,512].
// =============================================================================
__global__ __launch_bounds__(256)
void sim_bf(const __nv_bfloat16* __restrict__ hA, const __nv_bfloat16* __restrict__ hB,
            const int* __restrict__ mA, const int* __restrict__ mB,
            const float* __restrict__ temp,
            float* __restrict__ sAp, float* __restrict__ sB)
{
    __shared__ uint32_t As[2][8][SPAD];
    __shared__ uint32_t Bs[2][8][SPAD];
    __shared__ float rowmax[128];
    __shared__ float colmax[128];
    __shared__ int   smA[128];
    __shared__ int   smB[128];

    const int stile = blockIdx.x;
    const int b     = blockIdx.y;
    const int a     = blockIdx.z;
    const int tid  = threadIdx.x;
    const int wid  = tid >> 5;
    const int lane = tid & 31;
    const int g    = lane >> 2;
    const int tg   = lane & 3;
    const int m_base = (wid >> 2) * 64;
    const int n_base = (wid & 3) * 32;

    if (tid < 128) {
        rowmax[tid] = -FLT_MAX;
        colmax[tid] = -FLT_MAX;
        smA[tid] = mA[a * TA + tid];
        smB[tid] = mB[b * TB + stile * 128 + tid];
    }

    float acc[4][4][4];
    #pragma unroll
    for (int mt = 0; mt < 4; mt++)
        #pragma unroll
        for (int nt = 0; nt < 4; nt++)
            #pragma unroll
            for (int e = 0; e < 4; e++) acc[mt][nt][e] = 0.f;

    const int ar = tid >> 1;
    const int ah = (tid & 1) * 8;       // half offset
    const int ap = (tid & 1) * 4;       // pair row base
    const __nv_bfloat16* Ag = hA + (size_t)(a * TA + ar) * DEMB + ah;
    const __nv_bfloat16* Bg = hB + (size_t)(b * TB + stile * 128 + ar) * DEMB + ah;

    uint4 aq, bq;
    const int KT = DEMB / 16;   // 32

    aq = *(const uint4*)(Ag);
    bq = *(const uint4*)(Bg);
    As[0][ap + 0][ar] = aq.x; As[0][ap + 1][ar] = aq.y;
    As[0][ap + 2][ar] = aq.z; As[0][ap + 3][ar] = aq.w;
    Bs[0][ap + 0][ar] = bq.x; Bs[0][ap + 1][ar] = bq.y;
    Bs[0][ap + 2][ar] = bq.z; Bs[0][ap + 3][ar] = bq.w;
    __syncthreads();

    for (int kt = 0; kt < KT; kt++) {
        const int buf = kt & 1;
        if (kt + 1 < KT) {
            const int k0 = (kt + 1) * 16;
            aq = *(const uint4*)(Ag + k0);
            bq = *(const uint4*)(Bg + k0);
        }
        {
            uint32_t af[4][4], bf[4][2];
            #pragma unroll
            for (int mt = 0; mt < 4; mt++) {
                int m0 = m_base + mt * 16;
                af[mt][0] = As[buf][tg][m0 + g];
                af[mt][1] = As[buf][tg][m0 + g + 8];
                af[mt][2] = As[buf][tg + 4][m0 + g];
                af[mt][3] = As[buf][tg + 4][m0 + g + 8];
            }
            #pragma unroll
            for (int nt = 0; nt < 4; nt++) {
                int n0 = n_base + nt * 8;
                bf[nt][0] = Bs[buf][tg][n0 + g];
                bf[nt][1] = Bs[buf][tg + 4][n0 + g];
            }
            #pragma unroll
            for (int mt = 0; mt < 4; mt++)
                #pragma unroll
                for (int nt = 0; nt < 4; nt++)
                    mma_bf16(acc[mt][nt], af[mt][0], af[mt][1], af[mt][2], af[mt][3],
                             bf[nt][0], bf[nt][1]);
        }
        if (kt + 1 < KT) {
            const int nb = buf ^ 1;
            As[nb][ap + 0][ar] = aq.x; As[nb][ap + 1][ar] = aq.y;
            As[nb][ap + 2][ar] = aq.z; As[nb][ap + 3][ar] = aq.w;
            Bs[nb][ap + 0][ar] = bq.x; Bs[nb][ap + 1][ar] = bq.y;
            Bs[nb][ap + 2][ar] = bq.z; Bs[nb][ap + 3][ar] = bq.w;
            __syncthreads();
        }
    }

    // ---- fused masked max epilogue ----
    const float invT = 1.0f / temp[0];
    float rowm[4][2], colm[4][2];
    #pragma unroll
    for (int i = 0; i < 4; i++) {
        rowm[i][0] = rowm[i][1] = -FLT_MAX;
        colm[i][0] = colm[i][1] = -FLT_MAX;
    }
    #pragma unroll
    for (int mt = 0; mt < 4; mt++) {
        const int rl0 = m_base + mt * 16 + g;
        const int ma0 = smA[rl0];
        const int ma1 = smA[rl0 + 8];
        #pragma unroll
        for (int nt = 0; nt < 4; nt++) {
            const int cl0 = n_base + nt * 8 + tg * 2;
            const int mb0 = smB[cl0];
            const int mb1 = smB[cl0 + 1];
            float v00 = (ma0 && mb0) ? acc[mt][nt][0] * invT : -FLT_MAX;
            float v01 = (ma0 && mb1) ? acc[mt][nt][1] * invT : -FLT_MAX;
            float v10 = (ma1 && mb0) ? acc[mt][nt][2] * invT : -FLT_MAX;
            float v11 = (ma1 && mb1) ? acc[mt][nt][3] * invT : -FLT_MAX;
            rowm[mt][0] = fmaxf(rowm[mt][0], fmaxf(v00, v01));
            rowm[mt][1] = fmaxf(rowm[mt][1], fmaxf(v10, v11));
            colm[nt][0] = fmaxf(colm[nt][0], fmaxf(v00, v10));
            colm[nt][1] = fmaxf(colm[nt][1], fmaxf(v01, v11));
        }
    }
    #pragma unroll
    for (int mt = 0; mt < 4; mt++) {
        atomicMaxF(&rowmax[m_base + mt * 16 + g],     rowm[mt][0]);
        atomicMaxF(&rowmax[m_base + mt * 16 + g + 8], rowm[mt][1]);
    }
    #pragma unroll
    for (int nt = 0; nt < 4; nt++) {
        atomicMaxF(&colmax[n_base + nt * 8 + tg * 2],     colm[nt][0]);
        atomicMaxF(&colmax[n_base + nt * 8 + tg * 2 + 1], colm[nt][1]);
    }
    __syncthreads();

    if (tid < 128) {
        const int ab = a * BB + b;
        sAp[((size_t)ab * 8 + stile) * TA + tid] = rowmax[tid];
        sB[(size_t)ab * TB + stile * 128 + tid]  = colmax[tid];
    }
}

// ---------------- LayerNorm over last dim (512), one block per row ----------
__global__ __launch_bounds__(256)
void ln_kernel(float* __restrict__ H, const float* __restrict__ g,
               const float* __restrict__ b)
{
    __shared__ float sbuf[256];
    const int row = blockIdx.x;
    const int tid = threadIdx.x;
    float* h = H + (size_t)row * DEMB;
    float x0 = h[tid], x1 = h[tid + 256];
    float mu = blockReduceSum256(x0 + x1, sbuf) * (1.f / DEMB);
    float d0 = x0 - mu, d1 = x1 - mu;
    float var = blockReduceSum256(d0 * d0 + d1 * d1, sbuf) * (1.f / DEMB);
    float r = rsqrtf(var + 1e-5f);
    h[tid]       = d0 * r * g[tid]       + b[tid];
    h[tid + 256] = d1 * r * g[tid + 256] + b[tid + 256];
}

// ---------------- L2 row-normalize fp32 -> bf16, one block per row ----------
__global__ __launch_bounds__(256)
void rownorm_bf(const float* __restrict__ X, __nv_bfloat16* __restrict__ Y)
{
    __shared__ float sbuf[256];
    const int row = blockIdx.x;
    const int tid = threadIdx.x;
    const float* x = X + (size_t)row * DEMB;
    float x0 = x[tid], x1 = x[tid + 256];
    float s = blockReduceSum256(x0 * x0 + x1 * x1, sbuf);
    float inv = rsqrtf(s);
    __nv_bfloat16* y = Y + (size_t)row * DEMB;
    y[tid]       = __float2bfloat16(x0 * inv);
    y[tid + 256] = __float2bfloat16(x1 * inv);
}

// ---------------- finalize: masked means -> out [2,32,32] -------------------
__global__ __launch_bounds__(256)
void finalize_kernel(const float* __restrict__ sAp, const float* __restrict__ sB,
                     const int* __restrict__ mA, const int* __restrict__ mB,
                     float* __restrict__ out)
{
    __shared__ float sbuf[256];
    const int b = blockIdx.x;
    const int a = blockIdx.y;
    const int tid = threadIdx.x;
    const int ab = a * BB + b;

    float vA = 0.f, cA = 0.f;
    if (tid < TA) {
        const float* p = sAp + (size_t)ab * 8 * TA + tid;
        float m = p[0];
        #pragma unroll
        for (int t = 1; t < 8; t++) m = fmaxf(m, p[t * TA]);
        int msk = mA[a * TA + tid];
        vA = msk ? m : 0.f;
        cA = (float)msk;
    }
    float sumA = blockReduceSum256(vA, sbuf);
    float cntA = blockReduceSum256(cA, sbuf);

    float vB = 0.f, cB = 0.f;
    #pragma unroll
    for (int j = 0; j < 4; j++) {
        int s = tid + j * 256;
        int msk = mB[b * TB + s];
        float v = sB[(size_t)ab * TB + s];
        vB += msk ? v : 0.f;
        cB += (float)msk;
    }
    float sumB = blockReduceSum256(vB, sbuf);
    float cntB = blockReduceSum256(cB, sbuf);

    if (tid == 0) {
        out[ab]           = sumA / fmaxf(cntA, 1e-6f);
        out[BB * BB + ab] = sumB / fmaxf(cntB, 1e-6f);
    }
}

// ---------------- launch ----------------
extern "C" void kernel_launch(void* const* d_in, const int* in_sizes, int n_in,
                              void* d_out, int out_size)
{
    const float* pep_esm  = (const float*)d_in[0];
    const float* rec_esm  = (const float*)d_in[1];
    const int*   pep_mask = (const int*)d_in[2];
    const int*   rec_mask = (const int*)d_in[3];
    const float* temp     = (const float*)d_in[4];
    const float* pep_pw  = (const float*)d_in[5];
    const float* pep_pb  = (const float*)d_in[6];
    const float* pep_f1w = (const float*)d_in[7];
    const float* pep_f1b = (const float*)d_in[8];
    const float* pep_lng = (const float*)d_in[9];
    const float* pep_lnb = (const float*)d_in[10];
    const float* pep_f2w = (const float*)d_in[11];
    const float* pep_f2b = (const float*)d_in[12];
    const float* rec_pw  = (const float*)d_in[13];
    const float* rec_pb  = (const float*)d_in[14];
    const float* rec_f1w = (const float*)d_in[15];
    const float* rec_f1b = (const float*)d_in[16];
    const float* rec_lng = (const float*)d_in[17];
    const float* rec_lnb = (const float*)d_in[18];
    const float* rec_f2w = (const float*)d_in[19];
    const float* rec_f2b = (const float*)d_in[20];

    float *pE, *pH, *psAp, *psB;
    __nv_bfloat16 *phAb, *phBb;
    cudaGetSymbolAddress((void**)&pE,   g_E);
    cudaGetSymbolAddress((void**)&pH,   g_H);
    cudaGetSymbolAddress((void**)&phAb, g_hAb);
    cudaGetSymbolAddress((void**)&phBb, g_hBb);
    cudaGetSymbolAddress((void**)&psAp, g_sAp);
    cudaGetSymbolAddress((void**)&psB,  g_sB);

    // ---- pep encoder: M=4096 ----
    gemm_bf<false><<<dim3(DEMB / 128, MPEP / 128), 256>>>(pep_esm, pep_pw, pep_pb, pE, MPEP, DEMB, DIN);
    gemm_bf<true ><<<dim3(DEMB / 128, MPEP / 128), 256>>>(pE, pep_f1w, pep_f1b, pH, MPEP, DEMB, DEMB);
    ln_kernel<<<MPEP, 256>>>(pH, pep_lng, pep_lnb);
    gemm_bf<false><<<dim3(DEMB / 128, MPEP / 128), 256>>>(pH, pep_f2w, pep_f2b, pE, MPEP, DEMB, DEMB);
    rownorm_bf<<<MPEP, 256>>>(pE, phAb);

    // ---- rec encoder: M=32768 ----
    gemm_bf<false><<<dim3(DEMB / 128, MREC / 128), 256>>>(rec_esm, rec_pw, rec_pb, pE, MREC, DEMB, DIN);
    gemm_bf<true ><<<dim3(DEMB / 128, MREC / 128), 256>>>(pE, rec_f1w, rec_f1b, pH, MREC, DEMB, DEMB);
    ln_kernel<<<MREC, 256>>>(pH, rec_lng, rec_lnb);
    gemm_bf<false><<<dim3(DEMB / 128, MREC / 128), 256>>>(pH, rec_f2w, rec_f2b, pE, MREC, DEMB, DEMB);
    rownorm_bf<<<MREC, 256>>>(pE, phBb);

    // ---- fused sim + masked max ----
    sim_bf<<<dim3(TB / 128, BB, BB), 256>>>(phAb, phBb, pep_mask, rec_mask, temp, psAp, psB);

    // ---- masked means ----
    finalize_kernel<<<dim3(BB, BB), 256>>>(psAp, psB, pep_mask, rec_mask, (float*)d_out);
}

// round 12
// speedup vs baseline: 1.7911x; 1.0566x over previous
#include <cuda_runtime.h>
#include <cuda_bf16.h>
#include <cfloat>
#include <cstdint>

// ---------------- constants ----------------
#define BB    32
#define TA    128
#define TB    1024
#define DIN   1280
#define DEMB  512
#define MPEP  (BB*TA)       // 4096
#define MREC  (BB*TB)       // 32768
#define MTOT  (MPEP+MREC)   // 36864
#define PEPTILES (MPEP/128) // 32
#define SPAD  136           // u32 per smem pair-row (conflict-free fragment loads)

// ---------------- scratch (static device globals; no allocation) ------------
__device__ float g_E[MTOT * DEMB];               // fp32 merged intermediate (75.5 MB)
__device__ float g_H[MTOT * DEMB];               // fp32 merged intermediate (75.5 MB)
__device__ __nv_bfloat16 g_hAb[MPEP * DEMB];     // bf16 normalized pep (4 MB)
__device__ __nv_bfloat16 g_hBb[MREC * DEMB];     // bf16 normalized rec (32 MB)
__device__ float g_sAp[BB * BB * 8 * TA];
__device__ float g_sB[BB * BB * TB];

// ---------------- helpers ----------------
__device__ __forceinline__ void atomicMaxF(float* addr, float val) {
    if (val >= 0.f) atomicMax((int*)addr, __float_as_int(val));
    else            atomicMin((unsigned int*)addr, __float_as_uint(val));
}

__device__ __forceinline__ uint32_t pack_bf16(float lo, float hi) {
    __nv_bfloat162 h = __floats2bfloat162_rn(lo, hi);
    return *(uint32_t*)&h;
}

// m16n8k16 bf16 MMA, fp32 accumulate.
__device__ __forceinline__ void mma_bf16(float c[4],
    uint32_t a0, uint32_t a1, uint32_t a2, uint32_t a3,
    uint32_t b0, uint32_t b1)
{
    asm volatile(
        "mma.sync.aligned.m16n8k16.row.col.f32.bf16.bf16.f32 "
        "{%0,%1,%2,%3}, {%4,%5,%6,%7}, {%8,%9}, {%0,%1,%2,%3};"
        : "+f"(c[0]), "+f"(c[1]), "+f"(c[2]), "+f"(c[3])
        : "r"(a0), "r"(a1), "r"(a2), "r"(a3), "r"(b0), "r"(b1));
}

__device__ __forceinline__ float blockReduceSum256(float v, float* sbuf) {
    int tid = threadIdx.x;
    __syncthreads();
    sbuf[tid] = v;
    __syncthreads();
    #pragma unroll
    for (int s = 128; s > 0; s >>= 1) {
        if (tid < s) sbuf[tid] += sbuf[tid + s];
        __syncthreads();
    }
    float r = sbuf[0];
    __syncthreads();
    return r;
}

// =============================================================================
// Merged encoder GEMM: processes pep tiles (by < 32) and rec tiles (by >= 32)
// in ONE grid. C is the merged [MTOT, DEMB] buffer; A1 may carry a built-in
// row offset (pass A1 = merged_buf + MPEP*K for merged inputs).
// 128x128 block tile, Ktile=16 bf16 pairs, 256 thr = 8 warps (2m x 4n).
// Double-buffered smem, 1 sync/iter. __launch_bounds__(256,2): 2 CTAs/SM.
// =============================================================================
template<bool RELU>
__global__ __launch_bounds__(256, 2)
void gemm_enc(const float* __restrict__ A0, const float* __restrict__ A1,
              const float* __restrict__ W0, const float* __restrict__ W1,
              const float* __restrict__ bias0, const float* __restrict__ bias1,
              float* __restrict__ C, int K)
{
    __shared__ uint32_t As[2][8][SPAD];
    __shared__ uint32_t Bs[2][8][SPAD];

    const int N = DEMB;
    const int tid  = threadIdx.x;
    const int bx   = blockIdx.x;
    const int by   = blockIdx.y;
    const bool isPep = (by < PEPTILES);
    const float* A    = isPep ? A0 : A1;
    const float* W    = isPep ? W0 : W1;
    const float* bias = isPep ? bias0 : bias1;
    const int arow0 = (isPep ? by : (by - PEPTILES)) * 128;  // row within A source
    const int crow0 = by * 128;                               // row in merged C

    const int wid  = tid >> 5;
    const int lane = tid & 31;
    const int g    = lane >> 2;
    const int tg   = lane & 3;
    const int m_base = (wid >> 2) * 64;
    const int n_base = (wid & 3) * 32;

    float acc[4][4][4];
    #pragma unroll
    for (int mt = 0; mt < 4; mt++)
        #pragma unroll
        for (int nt = 0; nt < 4; nt++)
            #pragma unroll
            for (int e = 0; e < 4; e++) acc[mt][nt][e] = 0.f;

    // A loader: row ar, k halves ah..ah+7 (pair rows ap..ap+3)
    const int ar = tid >> 1;
    const int ah = (tid & 1) * 8;
    const int ap = (tid & 1) * 4;
    const float* Ag = A + (size_t)(arow0 + ar) * K + ah;
    // W loader: pair row pk (k rows 2pk, 2pk+1), 4 cols
    const int pk  = tid >> 5;
    const int bn4 = (tid & 31) * 4;
    const float* Bg = W + (size_t)(2 * pk) * N + bx * 128 + bn4;

    float a0[4], a1[4], blo[4], bhi[4];
    const int KT = K / 16;

    // ---- prologue: tile 0 ----
    *(float4*)a0  = *(const float4*)(Ag);
    *(float4*)a1  = *(const float4*)(Ag + 4);
    *(float4*)blo = *(const float4*)(Bg);
    *(float4*)bhi = *(const float4*)(Bg + N);
    {
        As[0][ap + 0][ar] = pack_bf16(a0[0], a0[1]);
        As[0][ap + 1][ar] = pack_bf16(a0[2], a0[3]);
        As[0][ap + 2][ar] = pack_bf16(a1[0], a1[1]);
        As[0][ap + 3][ar] = pack_bf16(a1[2], a1[3]);
        uint4 bv;
        bv.x = pack_bf16(blo[0], bhi[0]);
        bv.y = pack_bf16(blo[1], bhi[1]);
        bv.z = pack_bf16(blo[2], bhi[2]);
        bv.w = pack_bf16(blo[3], bhi[3]);
        *(uint4*)&Bs[0][pk][bn4] = bv;
    }
    __syncthreads();

    for (int kt = 0; kt < KT; kt++) {
        const int buf = kt & 1;
        if (kt + 1 < KT) {
            const int k0 = (kt + 1) * 16;
            *(float4*)a0  = *(const float4*)(Ag + k0);
            *(float4*)a1  = *(const float4*)(Ag + k0 + 4);
            *(float4*)blo = *(const float4*)(Bg + (size_t)k0 * N);
            *(float4*)bhi = *(const float4*)(Bg + (size_t)(k0 + 1) * N);
        }
        // ---- math: one m16n8k16 sweep covers the 16-k tile ----
        {
            uint32_t af[4][4], bf[4][2];
            #pragma unroll
            for (int mt = 0; mt < 4; mt++) {
                int m0 = m_base + mt * 16;
                af[mt][0] = As[buf][tg][m0 + g];
                af[mt][1] = As[buf][tg][m0 + g + 8];
                af[mt][2] = As[buf][tg + 4][m0 + g];
                af[mt][3] = As[buf][tg + 4][m0 + g + 8];
            }
            #pragma unroll
            for (int nt = 0; nt < 4; nt++) {
                int n0 = n_base + nt * 8;
                bf[nt][0] = Bs[buf][tg][n0 + g];
                bf[nt][1] = Bs[buf][tg + 4][n0 + g];
            }
            #pragma unroll
            for (int mt = 0; mt < 4; mt++)
                #pragma unroll
                for (int nt = 0; nt < 4; nt++)
                    mma_bf16(acc[mt][nt], af[mt][0], af[mt][1], af[mt][2], af[mt][3],
                             bf[nt][0], bf[nt][1]);
        }
        if (kt + 1 < KT) {
            const int nb = buf ^ 1;
            As[nb][ap + 0][ar] = pack_bf16(a0[0], a0[1]);
            As[nb][ap + 1][ar] = pack_bf16(a0[2], a0[3]);
            As[nb][ap + 2][ar] = pack_bf16(a1[0], a1[1]);
            As[nb][ap + 3][ar] = pack_bf16(a1[2], a1[3]);
            uint4 bv;
            bv.x = pack_bf16(blo[0], bhi[0]);
            bv.y = pack_bf16(blo[1], bhi[1]);
            bv.z = pack_bf16(blo[2], bhi[2]);
            bv.w = pack_bf16(blo[3], bhi[3]);
            *(uint4*)&Bs[nb][pk][bn4] = bv;
            __syncthreads();
        }
    }

    // ---- epilogue: bias + optional ReLU ----
    #pragma unroll
    for (int mt = 0; mt < 4; mt++) {
        const int row0 = crow0 + m_base + mt * 16 + g;
        #pragma unroll
        for (int nt = 0; nt < 4; nt++) {
            const int col = bx * 128 + n_base + nt * 8 + tg * 2;
            const float b0 = bias[col], b1 = bias[col + 1];
            float v0 = acc[mt][nt][0] + b0;
            float v1 = acc[mt][nt][1] + b1;
            float v2 = acc[mt][nt][2] + b0;
            float v3 = acc[mt][nt][3] + b1;
            if (RELU) {
                v0 = fmaxf(v0, 0.f); v1 = fmaxf(v1, 0.f);
                v2 = fmaxf(v2, 0.f); v3 = fmaxf(v3, 0.f);
            }
            *(float2*)&C[(size_t)row0 * N + col]       = make_float2(v0, v1);
            *(float2*)&C[(size_t)(row0 + 8) * N + col] = make_float2(v2, v3);
        }
    }
}

// =============================================================================
// bf16 sim GEMM + fused masked max. Operands already bf16 row-major [rows,512].
// =============================================================================
__global__ __launch_bounds__(256, 2)
void sim_bf(const __nv_bfloat16* __restrict__ hA, const __nv_bfloat16* __restrict__ hB,
            const int* __restrict__ mA, const int* __restrict__ mB,
            const float* __restrict__ temp,
            float* __restrict__ sAp, float* __restrict__ sB)
{
    __shared__ uint32_t As[2][8][SPAD];
    __shared__ uint32_t Bs[2][8][SPAD];
    __shared__ float rowmax[128];
    __shared__ float colmax[128];
    __shared__ int   smA[128];
    __shared__ int   smB[128];

    const int stile = blockIdx.x;
    const int b     = blockIdx.y;
    const int a     = blockIdx.z;
    const int tid  = threadIdx.x;
    const int wid  = tid >> 5;
    const int lane = tid & 31;
    const int g    = lane >> 2;
    const int tg   = lane & 3;
    const int m_base = (wid >> 2) * 64;
    const int n_base = (wid & 3) * 32;

    if (tid < 128) {
        rowmax[tid] = -FLT_MAX;
        colmax[tid] = -FLT_MAX;
        smA[tid] = mA[a * TA + tid];
        smB[tid] = mB[b * TB + stile * 128 + tid];
    }

    float acc[4][4][4];
    #pragma unroll
    for (int mt = 0; mt < 4; mt++)
        #pragma unroll
        for (int nt = 0; nt < 4; nt++)
            #pragma unroll
            for (int e = 0; e < 4; e++) acc[mt][nt][e] = 0.f;

    const int ar = tid >> 1;
    const int ah = (tid & 1) * 8;
    const int ap = (tid & 1) * 4;
    const __nv_bfloat16* Ag = hA + (size_t)(a * TA + ar) * DEMB + ah;
    const __nv_bfloat16* Bg = hB + (size_t)(b * TB + stile * 128 + ar) * DEMB + ah;

    uint4 aq, bq;
    const int KT = DEMB / 16;   // 32

    aq = *(const uint4*)(Ag);
    bq = *(const uint4*)(Bg);
    As[0][ap + 0][ar] = aq.x; As[0][ap + 1][ar] = aq.y;
    As[0][ap + 2][ar] = aq.z; As[0][ap + 3][ar] = aq.w;
    Bs[0][ap + 0][ar] = bq.x; Bs[0][ap + 1][ar] = bq.y;
    Bs[0][ap + 2][ar] = bq.z; Bs[0][ap + 3][ar] = bq.w;
    __syncthreads();

    for (int kt = 0; kt < KT; kt++) {
        const int buf = kt & 1;
        if (kt + 1 < KT) {
            const int k0 = (kt + 1) * 16;
            aq = *(const uint4*)(Ag + k0);
            bq = *(const uint4*)(Bg + k0);
        }
        {
            uint32_t af[4][4], bf[4][2];
            #pragma unroll
            for (int mt = 0; mt < 4; mt++) {
                int m0 = m_base + mt * 16;
                af[mt][0] = As[buf][tg][m0 + g];
                af[mt][1] = As[buf][tg][m0 + g + 8];
                af[mt][2] = As[buf][tg + 4][m0 + g];
                af[mt][3] = As[buf][tg + 4][m0 + g + 8];
            }
            #pragma unroll
            for (int nt = 0; nt < 4; nt++) {
                int n0 = n_base + nt * 8;
                bf[nt][0] = Bs[buf][tg][n0 + g];
                bf[nt][1] = Bs[buf][tg + 4][n0 + g];
            }
            #pragma unroll
            for (int mt = 0; mt < 4; mt++)
                #pragma unroll
                for (int nt = 0; nt < 4; nt++)
                    mma_bf16(acc[mt][nt], af[mt][0], af[mt][1], af[mt][2], af[mt][3],
                             bf[nt][0], bf[nt][1]);
        }
        if (kt + 1 < KT) {
            const int nb = buf ^ 1;
            As[nb][ap + 0][ar] = aq.x; As[nb][ap + 1][ar] = aq.y;
            As[nb][ap + 2][ar] = aq.z; As[nb][ap + 3][ar] = aq.w;
            Bs[nb][ap + 0][ar] = bq.x; Bs[nb][ap + 1][ar] = bq.y;
            Bs[nb][ap + 2][ar] = bq.z; Bs[nb][ap + 3][ar] = bq.w;
            __syncthreads();
        }
    }

    // ---- fused masked max epilogue ----
    const float invT = 1.0f / temp[0];
    float rowm[4][2], colm[4][2];
    #pragma unroll
    for (int i = 0; i < 4; i++) {
        rowm[i][0] = rowm[i][1] = -FLT_MAX;
        colm[i][0] = colm[i][1] = -FLT_MAX;
    }
    #pragma unroll
    for (int mt = 0; mt < 4; mt++) {
        const int rl0 = m_base + mt * 16 + g;
        const int ma0 = smA[rl0];
        const int ma1 = smA[rl0 + 8];
        #pragma unroll
        for (int nt = 0; nt < 4; nt++) {
            const int cl0 = n_base + nt * 8 + tg * 2;
            const int mb0 = smB[cl0];
            const int mb1 = smB[cl0 + 1];
            float v00 = (ma0 && mb0) ? acc[mt][nt][0] * invT : -FLT_MAX;
            float v01 = (ma0 && mb1) ? acc[mt][nt][1] * invT : -FLT_MAX;
            float v10 = (ma1 && mb0) ? acc[mt][nt][2] * invT : -FLT_MAX;
            float v11 = (ma1 && mb1) ? acc[mt][nt][3] * invT : -FLT_MAX;
            rowm[mt][0] = fmaxf(rowm[mt][0], fmaxf(v00, v01));
            rowm[mt][1] = fmaxf(rowm[mt][1], fmaxf(v10, v11));
            colm[nt][0] = fmaxf(colm[nt][0], fmaxf(v00, v10));
            colm[nt][1] = fmaxf(colm[nt][1], fmaxf(v01, v11));
        }
    }
    #pragma unroll
    for (int mt = 0; mt < 4; mt++) {
        atomicMaxF(&rowmax[m_base + mt * 16 + g],     rowm[mt][0]);
        atomicMaxF(&rowmax[m_base + mt * 16 + g + 8], rowm[mt][1]);
    }
    #pragma unroll
    for (int nt = 0; nt < 4; nt++) {
        atomicMaxF(&colmax[n_base + nt * 8 + tg * 2],     colm[nt][0]);
        atomicMaxF(&colmax[n_base + nt * 8 + tg * 2 + 1], colm[nt][1]);
    }
    __syncthreads();

    if (tid < 128) {
        const int ab = a * BB + b;
        sAp[((size_t)ab * 8 + stile) * TA + tid] = rowmax[tid];
        sB[(size_t)ab * TB + stile * 128 + tid]  = colmax[tid];
    }
}

// ---------------- merged LayerNorm: per-row g/b select -----------------------
__global__ __launch_bounds__(256, 2)
void ln_merged(float* __restrict__ H,
               const float* __restrict__ g0, const float* __restrict__ b0,
               const float* __restrict__ g1, const float* __restrict__ b1)
{
    __shared__ float sbuf[256];
    const int row = blockIdx.x;
    const int tid = threadIdx.x;
    const float* g = (row < MPEP) ? g0 : g1;
    const float* b = (row < MPEP) ? b0 : b1;
    float* h = H + (size_t)row * DEMB;
    float x0 = h[tid], x1 = h[tid + 256];
    float mu = blockReduceSum256(x0 + x1, sbuf) * (1.f / DEMB);
    float d0 = x0 - mu, d1 = x1 - mu;
    float var = blockReduceSum256(d0 * d0 + d1 * d1, sbuf) * (1.f / DEMB);
    float r = rsqrtf(var + 1e-5f);
    h[tid]       = d0 * r * g[tid]       + b[tid];
    h[tid + 256] = d1 * r * g[tid + 256] + b[tid + 256];
}

// ---------------- merged L2 row-normalize fp32 -> bf16 ------------------------
__global__ __launch_bounds__(256, 2)
void rownorm_merged(const float* __restrict__ X,
                    __nv_bfloat16* __restrict__ YA, __nv_bfloat16* __restrict__ YB)
{
    __shared__ float sbuf[256];
    const int row = blockIdx.x;
    const int tid = threadIdx.x;
    const float* x = X + (size_t)row * DEMB;
    float x0 = x[tid], x1 = x[tid + 256];
    float s = blockReduceSum256(x0 * x0 + x1 * x1, sbuf);
    float inv = rsqrtf(s);
    __nv_bfloat16* y = (row < MPEP) ? (YA + (size_t)row * DEMB)
                                    : (YB + (size_t)(row - MPEP) * DEMB);
    y[tid]       = __float2bfloat16(x0 * inv);
    y[tid + 256] = __float2bfloat16(x1 * inv);
}

// ---------------- finalize: masked means -> out [2,32,32] -------------------
__global__ __launch_bounds__(256)
void finalize_kernel(const float* __restrict__ sAp, const float* __restrict__ sB,
                     const int* __restrict__ mA, const int* __restrict__ mB,
                     float* __restrict__ out)
{
    __shared__ float sbuf[256];
    const int b = blockIdx.x;
    const int a = blockIdx.y;
    const int tid = threadIdx.x;
    const int ab = a * BB + b;

    float vA = 0.f, cA = 0.f;
    if (tid < TA) {
        const float* p = sAp + (size_t)ab * 8 * TA + tid;
        float m = p[0];
        #pragma unroll
        for (int t = 1; t < 8; t++) m = fmaxf(m, p[t * TA]);
        int msk = mA[a * TA + tid];
        vA = msk ? m : 0.f;
        cA = (float)msk;
    }
    float sumA = blockReduceSum256(vA, sbuf);
    float cntA = blockReduceSum256(cA, sbuf);

    float vB = 0.f, cB = 0.f;
    #pragma unroll
    for (int j = 0; j < 4; j++) {
        int s = tid + j * 256;
        int msk = mB[b * TB + s];
        float v = sB[(size_t)ab * TB + s];
        vB += msk ? v : 0.f;
        cB += (float)msk;
    }
    float sumB = blockReduceSum256(vB, sbuf);
    float cntB = blockReduceSum256(cB, sbuf);

    if (tid == 0) {
        out[ab]           = sumA / fmaxf(cntA, 1e-6f);
        out[BB * BB + ab] = sumB / fmaxf(cntB, 1e-6f);
    }
}

// ---------------- launch ----------------
extern "C" void kernel_launch(void* const* d_in, const int* in_sizes, int n_in,
                              void* d_out, int out_size)
{
    const float* pep_esm  = (const float*)d_in[0];
    const float* rec_esm  = (const float*)d_in[1];
    const int*   pep_mask = (const int*)d_in[2];
    const int*   rec_mask = (const int*)d_in[3];
    const float* temp     = (const float*)d_in[4];
    const float* pep_pw  = (const float*)d_in[5];
    const float* pep_pb  = (const float*)d_in[6];
    const float* pep_f1w = (const float*)d_in[7];
    const float* pep_f1b = (const float*)d_in[8];
    const float* pep_lng = (const float*)d_in[9];
    const float* pep_lnb = (const float*)d_in[10];
    const float* pep_f2w = (const float*)d_in[11];
    const float* pep_f2b = (const float*)d_in[12];
    const float* rec_pw  = (const float*)d_in[13];
    const float* rec_pb  = (const float*)d_in[14];
    const float* rec_f1w = (const float*)d_in[15];
    const float* rec_f1b = (const float*)d_in[16];
    const float* rec_lng = (const float*)d_in[17];
    const float* rec_lnb = (const float*)d_in[18];
    const float* rec_f2w = (const float*)d_in[19];
    const float* rec_f2b = (const float*)d_in[20];

    float *pE, *pH, *psAp, *psB;
    __nv_bfloat16 *phAb, *phBb;
    cudaGetSymbolAddress((void**)&pE,   g_E);
    cudaGetSymbolAddress((void**)&pH,   g_H);
    cudaGetSymbolAddress((void**)&phAb, g_hAb);
    cudaGetSymbolAddress((void**)&phBb, g_hBb);
    cudaGetSymbolAddress((void**)&psAp, g_sAp);
    cudaGetSymbolAddress((void**)&psB,  g_sB);

    const dim3 encGrid(DEMB / 128, MTOT / 128);   // (4, 288)

    // ---- merged encoders: pep tiles (by<32) + rec tiles (by>=32) ----
    gemm_enc<false><<<encGrid, 256>>>(pep_esm, rec_esm, pep_pw, rec_pw,
                                      pep_pb, rec_pb, pE, DIN);
    gemm_enc<true ><<<encGrid, 256>>>(pE, pE + (size_t)MPEP * DEMB,
                                      pep_f1w, rec_f1w, pep_f1b, rec_f1b, pH, DEMB);
    ln_merged<<<MTOT, 256>>>(pH, pep_lng, pep_lnb, rec_lng, rec_lnb);
    gemm_enc<false><<<encGrid, 256>>>(pH, pH + (size_t)MPEP * DEMB,
                                      pep_f2w, rec_f2w, pep_f2b, rec_f2b, pE, DEMB);
    rownorm_merged<<<MTOT, 256>>>(pE, phAb, phBb);

    // ---- fused sim + masked max ----
    sim_bf<<<dim3(TB / 128, BB, BB), 256>>>(phAb, phBb, pep_mask, rec_mask, temp, psAp, psB);

    // ---- masked means ----
    finalize_kernel<<<dim3(BB, BB), 256>>>(psAp, psB, pep_mask, rec_mask, (float*)d_out);
}

// round 13
// speedup vs baseline: 1.9477x; 1.0874x over previous
#include <cuda_runtime.h>
#include <cuda_bf16.h>
#include <cfloat>
#include <cstdint>

// ---------------- constants ----------------
#define BB    32
#define TA    128
#define TB    1024
#define DIN   1280
#define DEMB  512
#define MPEP  (BB*TA)       // 4096
#define MREC  (BB*TB)       // 32768
#define MTOT  (MPEP+MREC)   // 36864
#define PEPTILES (MPEP/128) // 32
#define SPAD  136           // u32 per smem pair-row (encoder kernels)
#define SROW  12            // u32 per m-row in sim pipeline smem (8 data + 4 pad)
#define STAGES 3

// ---------------- scratch (static device globals; no allocation) ------------
__device__ float g_E[MTOT * DEMB];
__device__ float g_H[MTOT * DEMB];
__device__ __nv_bfloat16 g_hAb[MPEP * DEMB];
__device__ __nv_bfloat16 g_hBb[MREC * DEMB];
__device__ float g_sAp[BB * BB * 8 * TA];
__device__ float g_sB[BB * BB * TB];

// ---------------- helpers ----------------
__device__ __forceinline__ void atomicMaxF(float* addr, float val) {
    if (val >= 0.f) atomicMax((int*)addr, __float_as_int(val));
    else            atomicMin((unsigned int*)addr, __float_as_uint(val));
}

__device__ __forceinline__ uint32_t pack_bf16(float lo, float hi) {
    __nv_bfloat162 h = __floats2bfloat162_rn(lo, hi);
    return *(uint32_t*)&h;
}

__device__ __forceinline__ void mma_bf16(float c[4],
    uint32_t a0, uint32_t a1, uint32_t a2, uint32_t a3,
    uint32_t b0, uint32_t b1)
{
    asm volatile(
        "mma.sync.aligned.m16n8k16.row.col.f32.bf16.bf16.f32 "
        "{%0,%1,%2,%3}, {%4,%5,%6,%7}, {%8,%9}, {%0,%1,%2,%3};"
        : "+f"(c[0]), "+f"(c[1]), "+f"(c[2]), "+f"(c[3])
        : "r"(a0), "r"(a1), "r"(a2), "r"(a3), "r"(b0), "r"(b1));
}

__device__ __forceinline__ void cp_async16(uint32_t smem_addr, const void* gptr) {
    asm volatile("cp.async.cg.shared.global [%0], [%1], 16;\n"
                 :: "r"(smem_addr), "l"(gptr));
}
__device__ __forceinline__ void cp_commit() {
    asm volatile("cp.async.commit_group;\n" ::: "memory");
}
__device__ __forceinline__ void cp_wait1() {
    asm volatile("cp.async.wait_group 1;\n" ::: "memory");
}

__device__ __forceinline__ float blockReduceSum256(float v, float* sbuf) {
    int tid = threadIdx.x;
    __syncthreads();
    sbuf[tid] = v;
    __syncthreads();
    #pragma unroll
    for (int s = 128; s > 0; s >>= 1) {
        if (tid < s) sbuf[tid] += sbuf[tid + s];
        __syncthreads();
    }
    float r = sbuf[0];
    __syncthreads();
    return r;
}

// =============================================================================
// Merged encoder GEMM (unchanged from R12, verified at 1325 µs run).
// =============================================================================
template<bool RELU>
__global__ __launch_bounds__(256, 2)
void gemm_enc(const float* __restrict__ A0, const float* __restrict__ A1,
              const float* __restrict__ W0, const float* __restrict__ W1,
              const float* __restrict__ bias0, const float* __restrict__ bias1,
              float* __restrict__ C, int K)
{
    __shared__ uint32_t As[2][8][SPAD];
    __shared__ uint32_t Bs[2][8][SPAD];

    const int N = DEMB;
    const int tid  = threadIdx.x;
    const int bx   = blockIdx.x;
    const int by   = blockIdx.y;
    const bool isPep = (by < PEPTILES);
    const float* A    = isPep ? A0 : A1;
    const float* W    = isPep ? W0 : W1;
    const float* bias = isPep ? bias0 : bias1;
    const int arow0 = (isPep ? by : (by - PEPTILES)) * 128;
    const int crow0 = by * 128;

    const int wid  = tid >> 5;
    const int lane = tid & 31;
    const int g    = lane >> 2;
    const int tg   = lane & 3;
    const int m_base = (wid >> 2) * 64;
    const int n_base = (wid & 3) * 32;

    float acc[4][4][4];
    #pragma unroll
    for (int mt = 0; mt < 4; mt++)
        #pragma unroll
        for (int nt = 0; nt < 4; nt++)
            #pragma unroll
            for (int e = 0; e < 4; e++) acc[mt][nt][e] = 0.f;

    const int ar = tid >> 1;
    const int ah = (tid & 1) * 8;
    const int ap = (tid & 1) * 4;
    const float* Ag = A + (size_t)(arow0 + ar) * K + ah;
    const int pk  = tid >> 5;
    const int bn4 = (tid & 31) * 4;
    const float* Bg = W + (size_t)(2 * pk) * N + bx * 128 + bn4;

    float a0[4], a1[4], blo[4], bhi[4];
    const int KT = K / 16;

    *(float4*)a0  = *(const float4*)(Ag);
    *(float4*)a1  = *(const float4*)(Ag + 4);
    *(float4*)blo = *(const float4*)(Bg);
    *(float4*)bhi = *(const float4*)(Bg + N);
    {
        As[0][ap + 0][ar] = pack_bf16(a0[0], a0[1]);
        As[0][ap + 1][ar] = pack_bf16(a0[2], a0[3]);
        As[0][ap + 2][ar] = pack_bf16(a1[0], a1[1]);
        As[0][ap + 3][ar] = pack_bf16(a1[2], a1[3]);
        uint4 bv;
        bv.x = pack_bf16(blo[0], bhi[0]);
        bv.y = pack_bf16(blo[1], bhi[1]);
        bv.z = pack_bf16(blo[2], bhi[2]);
        bv.w = pack_bf16(blo[3], bhi[3]);
        *(uint4*)&Bs[0][pk][bn4] = bv;
    }
    __syncthreads();

    for (int kt = 0; kt < KT; kt++) {
        const int buf = kt & 1;
        if (kt + 1 < KT) {
            const int k0 = (kt + 1) * 16;
            *(float4*)a0  = *(const float4*)(Ag + k0);
            *(float4*)a1  = *(const float4*)(Ag + k0 + 4);
            *(float4*)blo = *(const float4*)(Bg + (size_t)k0 * N);
            *(float4*)bhi = *(const float4*)(Bg + (size_t)(k0 + 1) * N);
        }
        {
            uint32_t af[4][4], bf[4][2];
            #pragma unroll
            for (int mt = 0; mt < 4; mt++) {
                int m0 = m_base + mt * 16;
                af[mt][0] = As[buf][tg][m0 + g];
                af[mt][1] = As[buf][tg][m0 + g + 8];
                af[mt][2] = As[buf][tg + 4][m0 + g];
                af[mt][3] = As[buf][tg + 4][m0 + g + 8];
            }
            #pragma unroll
            for (int nt = 0; nt < 4; nt++) {
                int n0 = n_base + nt * 8;
                bf[nt][0] = Bs[buf][tg][n0 + g];
                bf[nt][1] = Bs[buf][tg + 4][n0 + g];
            }
            #pragma unroll
            for (int mt = 0; mt < 4; mt++)
                #pragma unroll
                for (int nt = 0; nt < 4; nt++)
                    mma_bf16(acc[mt][nt], af[mt][0], af[mt][1], af[mt][2], af[mt][3],
                             bf[nt][0], bf[nt][1]);
        }
        if (kt + 1 < KT) {
            const int nb = buf ^ 1;
            As[nb][ap + 0][ar] = pack_bf16(a0[0], a0[1]);
            As[nb][ap + 1][ar] = pack_bf16(a0[2], a0[3]);
            As[nb][ap + 2][ar] = pack_bf16(a1[0], a1[1]);
            As[nb][ap + 3][ar] = pack_bf16(a1[2], a1[3]);
            uint4 bv;
            bv.x = pack_bf16(blo[0], bhi[0]);
            bv.y = pack_bf16(blo[1], bhi[1]);
            bv.z = pack_bf16(blo[2], bhi[2]);
            bv.w = pack_bf16(blo[3], bhi[3]);
            *(uint4*)&Bs[nb][pk][bn4] = bv;
            __syncthreads();
        }
    }

    #pragma unroll
    for (int mt = 0; mt < 4; mt++) {
        const int row0 = crow0 + m_base + mt * 16 + g;
        #pragma unroll
        for (int nt = 0; nt < 4; nt++) {
            const int col = bx * 128 + n_base + nt * 8 + tg * 2;
            const float b0 = bias[col], b1 = bias[col + 1];
            float v0 = acc[mt][nt][0] + b0;
            float v1 = acc[mt][nt][1] + b1;
            float v2 = acc[mt][nt][2] + b0;
            float v3 = acc[mt][nt][3] + b1;
            if (RELU) {
                v0 = fmaxf(v0, 0.f); v1 = fmaxf(v1, 0.f);
                v2 = fmaxf(v2, 0.f); v3 = fmaxf(v3, 0.f);
            }
            *(float2*)&C[(size_t)row0 * N + col]       = make_float2(v0, v1);
            *(float2*)&C[(size_t)(row0 + 8) * N + col] = make_float2(v2, v3);
        }
    }
}

// =============================================================================
// sim GEMM, cp.async 3-stage pipeline + fused masked max with shfl-reduced
// atomics. Smem layout: X[stage][m*SROW + pair], pair = k/2 (bf16x2), SROW=12.
// Bank map for fragment LDS: (m0+g)*12+tg mod 32 -> 32 distinct banks.
// =============================================================================
__global__ __launch_bounds__(256, 2)
void sim_bf(const __nv_bfloat16* __restrict__ hA, const __nv_bfloat16* __restrict__ hB,
            const int* __restrict__ mA, const int* __restrict__ mB,
            const float* __restrict__ temp,
            float* __restrict__ sAp, float* __restrict__ sB)
{
    __shared__ uint32_t As[STAGES][128 * SROW];
    __shared__ uint32_t Bs[STAGES][128 * SROW];
    __shared__ float rowmax[128];
    __shared__ float colmax[128];
    __shared__ int   smA[128];
    __shared__ int   smB[128];

    const int stile = blockIdx.x;
    const int b     = blockIdx.y;
    const int a     = blockIdx.z;
    const int tid  = threadIdx.x;
    const int wid  = tid >> 5;
    const int lane = tid & 31;
    const int g    = lane >> 2;
    const int tg   = lane & 3;
    const int m_base = (wid >> 2) * 64;
    const int n_base = (wid & 3) * 32;

    if (tid < 128) {
        rowmax[tid] = -FLT_MAX;
        colmax[tid] = -FLT_MAX;
        smA[tid] = mA[a * TA + tid];
        smB[tid] = mB[b * TB + stile * 128 + tid];
    }
    __syncthreads();   // smA/smB + rowmax/colmax visible before epilogue usage

    float acc[4][4][4];
    #pragma unroll
    for (int mt = 0; mt < 4; mt++)
        #pragma unroll
        for (int nt = 0; nt < 4; nt++)
            #pragma unroll
            for (int e = 0; e < 4; e++) acc[mt][nt][e] = 0.f;

    // loader mapping: row lr = tid>>1 (0..127), chunk c = tid&1 (8 bf16 = 16B)
    const int lr = tid >> 1;
    const int lc = tid & 1;
    const __nv_bfloat16* Ag = hA + (size_t)(a * TA + lr) * DEMB + lc * 8;
    const __nv_bfloat16* Bg = hB + (size_t)(b * TB + stile * 128 + lr) * DEMB + lc * 8;
    // smem dst (u32 units): lr*SROW + lc*4
    const uint32_t dstOff = (uint32_t)(lr * SROW + lc * 4) * 4;  // bytes
    uint32_t aBase = (uint32_t)__cvta_generic_to_shared(&As[0][0]);
    uint32_t bBase = (uint32_t)__cvta_generic_to_shared(&Bs[0][0]);
    const uint32_t stageBytes = 128 * SROW * 4;

    const int KT = DEMB / 16;   // 32

    // ---- prologue: issue tiles 0 and 1 ----
    #pragma unroll
    for (int t = 0; t < 2; t++) {
        cp_async16(aBase + t * stageBytes + dstOff, Ag + t * 16);
        cp_async16(bBase + t * stageBytes + dstOff, Bg + t * 16);
        cp_commit();
    }

    int stage = 0;
    for (int kt = 0; kt < KT; kt++) {
        cp_wait1();
        __syncthreads();

        // issue tile kt+2 into stage (kt+2)%3 ; always commit (group accounting)
        if (kt + 2 < KT) {
            int ws = stage + 2; if (ws >= STAGES) ws -= STAGES;
            cp_async16(aBase + ws * stageBytes + dstOff, Ag + (kt + 2) * 16);
            cp_async16(bBase + ws * stageBytes + dstOff, Bg + (kt + 2) * 16);
        }
        cp_commit();

        // ---- math on stage ----
        const uint32_t* Asb = As[stage];
        const uint32_t* Bsb = Bs[stage];
        uint32_t af[4][4], bf[4][2];
        #pragma unroll
        for (int mt = 0; mt < 4; mt++) {
            int m0 = m_base + mt * 16;
            af[mt][0] = Asb[(m0 + g) * SROW + tg];
            af[mt][1] = Asb[(m0 + g + 8) * SROW + tg];
            af[mt][2] = Asb[(m0 + g) * SROW + tg + 4];
            af[mt][3] = Asb[(m0 + g + 8) * SROW + tg + 4];
        }
        #pragma unroll
        for (int nt = 0; nt < 4; nt++) {
            int n0 = n_base + nt * 8;
            bf[nt][0] = Bsb[(n0 + g) * SROW + tg];
            bf[nt][1] = Bsb[(n0 + g) * SROW + tg + 4];
        }
        #pragma unroll
        for (int mt = 0; mt < 4; mt++)
            #pragma unroll
            for (int nt = 0; nt < 4; nt++)
                mma_bf16(acc[mt][nt], af[mt][0], af[mt][1], af[mt][2], af[mt][3],
                         bf[nt][0], bf[nt][1]);

        stage = stage + 1; if (stage >= STAGES) stage = 0;
    }

    // ---- fused masked max epilogue (shfl pre-reduction, then sparse atomics) --
    const float invT = 1.0f / temp[0];
    float rowm[4][2], colm[4][2];
    #pragma unroll
    for (int i = 0; i < 4; i++) {
        rowm[i][0] = rowm[i][1] = -FLT_MAX;
        colm[i][0] = colm[i][1] = -FLT_MAX;
    }
    #pragma unroll
    for (int mt = 0; mt < 4; mt++) {
        const int rl0 = m_base + mt * 16 + g;
        const int ma0 = smA[rl0];
        const int ma1 = smA[rl0 + 8];
        #pragma unroll
        for (int nt = 0; nt < 4; nt++) {
            const int cl0 = n_base + nt * 8 + tg * 2;
            const int mb0 = smB[cl0];
            const int mb1 = smB[cl0 + 1];
            float v00 = (ma0 && mb0) ? acc[mt][nt][0] * invT : -FLT_MAX;
            float v01 = (ma0 && mb1) ? acc[mt][nt][1] * invT : -FLT_MAX;
            float v10 = (ma1 && mb0) ? acc[mt][nt][2] * invT : -FLT_MAX;
            float v11 = (ma1 && mb1) ? acc[mt][nt][3] * invT : -FLT_MAX;
            rowm[mt][0] = fmaxf(rowm[mt][0], fmaxf(v00, v01));
            rowm[mt][1] = fmaxf(rowm[mt][1], fmaxf(v10, v11));
            colm[nt][0] = fmaxf(colm[nt][0], fmaxf(v00, v10));
            colm[nt][1] = fmaxf(colm[nt][1], fmaxf(v01, v11));
        }
    }
    // rowm: value depends on (g, tg); row id depends only on g -> reduce over tg
    #pragma unroll
    for (int mt = 0; mt < 4; mt++)
        #pragma unroll
        for (int h = 0; h < 2; h++) {
            float v = rowm[mt][h];
            v = fmaxf(v, __shfl_xor_sync(0xFFFFFFFF, v, 1));
            v = fmaxf(v, __shfl_xor_sync(0xFFFFFFFF, v, 2));
            if (tg == 0)
                atomicMaxF(&rowmax[m_base + mt * 16 + g + h * 8], v);
        }
    // colm: col id depends only on tg (and pair bit) -> reduce over g
    #pragma unroll
    for (int nt = 0; nt < 4; nt++)
        #pragma unroll
        for (int p = 0; p < 2; p++) {
            float v = colm[nt][p];
            v = fmaxf(v, __shfl_xor_sync(0xFFFFFFFF, v, 4));
            v = fmaxf(v, __shfl_xor_sync(0xFFFFFFFF, v, 8));
            v = fmaxf(v, __shfl_xor_sync(0xFFFFFFFF, v, 16));
            if (g == 0)
                atomicMaxF(&colmax[n_base + nt * 8 + tg * 2 + p], v);
        }
    __syncthreads();

    if (tid < 128) {
        const int ab = a * BB + b;
        sAp[((size_t)ab * 8 + stile) * TA + tid] = rowmax[tid];
        sB[(size_t)ab * TB + stile * 128 + tid]  = colmax[tid];
    }
}

// ---------------- merged LayerNorm ----------------
__global__ __launch_bounds__(256, 2)
void ln_merged(float* __restrict__ H,
               const float* __restrict__ g0, const float* __restrict__ b0,
               const float* __restrict__ g1, const float* __restrict__ b1)
{
    __shared__ float sbuf[256];
    const int row = blockIdx.x;
    const int tid = threadIdx.x;
    const float* g = (row < MPEP) ? g0 : g1;
    const float* b = (row < MPEP) ? b0 : b1;
    float* h = H + (size_t)row * DEMB;
    float x0 = h[tid], x1 = h[tid + 256];
    float mu = blockReduceSum256(x0 + x1, sbuf) * (1.f / DEMB);
    float d0 = x0 - mu, d1 = x1 - mu;
    float var = blockReduceSum256(d0 * d0 + d1 * d1, sbuf) * (1.f / DEMB);
    float r = rsqrtf(var + 1e-5f);
    h[tid]       = d0 * r * g[tid]       + b[tid];
    h[tid + 256] = d1 * r * g[tid + 256] + b[tid + 256];
}

// ---------------- merged L2 row-normalize fp32 -> bf16 ------------------------
__global__ __launch_bounds__(256, 2)
void rownorm_merged(const float* __restrict__ X,
                    __nv_bfloat16* __restrict__ YA, __nv_bfloat16* __restrict__ YB)
{
    __shared__ float sbuf[256];
    const int row = blockIdx.x;
    const int tid = threadIdx.x;
    const float* x = X + (size_t)row * DEMB;
    float x0 = x[tid], x1 = x[tid + 256];
    float s = blockReduceSum256(x0 * x0 + x1 * x1, sbuf);
    float inv = rsqrtf(s);
    __nv_bfloat16* y = (row < MPEP) ? (YA + (size_t)row * DEMB)
                                    : (YB + (size_t)(row - MPEP) * DEMB);
    y[tid]       = __float2bfloat16(x0 * inv);
    y[tid + 256] = __float2bfloat16(x1 * inv);
}

// ---------------- finalize ----------------
__global__ __launch_bounds__(256)
void finalize_kernel(const float* __restrict__ sAp, const float* __restrict__ sB,
                     const int* __restrict__ mA, const int* __restrict__ mB,
                     float* __restrict__ out)
{
    __shared__ float sbuf[256];
    const int b = blockIdx.x;
    const int a = blockIdx.y;
    const int tid = threadIdx.x;
    const int ab = a * BB + b;

    float vA = 0.f, cA = 0.f;
    if (tid < TA) {
        const float* p = sAp + (size_t)ab * 8 * TA + tid;
        float m = p[0];
        #pragma unroll
        for (int t = 1; t < 8; t++) m = fmaxf(m, p[t * TA]);
        int msk = mA[a * TA + tid];
        vA = msk ? m : 0.f;
        cA = (float)msk;
    }
    float sumA = blockReduceSum256(vA, sbuf);
    float cntA = blockReduceSum256(cA, sbuf);

    float vB = 0.f, cB = 0.f;
    #pragma unroll
    for (int j = 0; j < 4; j++) {
        int s = tid + j * 256;
        int msk = mB[b * TB + s];
        float v = sB[(size_t)ab * TB + s];
        vB += msk ? v : 0.f;
        cB += (float)msk;
    }
    float sumB = blockReduceSum256(vB, sbuf);
    float cntB = blockReduceSum256(cB, sbuf);

    if (tid == 0) {
        out[ab]           = sumA / fmaxf(cntA, 1e-6f);
        out[BB * BB + ab] = sumB / fmaxf(cntB, 1e-6f);
    }
}

// ---------------- launch ----------------
extern "C" void kernel_launch(void* const* d_in, const int* in_sizes, int n_in,
                              void* d_out, int out_size)
{
    const float* pep_esm  = (const float*)d_in[0];
    const float* rec_esm  = (const float*)d_in[1];
    const int*   pep_mask = (const int*)d_in[2];
    const int*   rec_mask = (const int*)d_in[3];
    const float* temp     = (const float*)d_in[4];
    const float* pep_pw  = (const float*)d_in[5];
    const float* pep_pb  = (const float*)d_in[6];
    const float* pep_f1w = (const float*)d_in[7];
    const float* pep_f1b = (const float*)d_in[8];
    const float* pep_lng = (const float*)d_in[9];
    const float* pep_lnb = (const float*)d_in[10];
    const float* pep_f2w = (const float*)d_in[11];
    const float* pep_f2b = (const float*)d_in[12];
    const float* rec_pw  = (const float*)d_in[13];
    const float* rec_pb  = (const float*)d_in[14];
    const float* rec_f1w = (const float*)d_in[15];
    const float* rec_f1b = (const float*)d_in[16];
    const float* rec_lng = (const float*)d_in[17];
    const float* rec_lnb = (const float*)d_in[18];
    const float* rec_f2w = (const float*)d_in[19];
    const float* rec_f2b = (const float*)d_in[20];

    float *pE, *pH, *psAp, *psB;
    __nv_bfloat16 *phAb, *phBb;
    cudaGetSymbolAddress((void**)&pE,   g_E);
    cudaGetSymbolAddress((void**)&pH,   g_H);
    cudaGetSymbolAddress((void**)&phAb, g_hAb);
    cudaGetSymbolAddress((void**)&phBb, g_hBb);
    cudaGetSymbolAddress((void**)&psAp, g_sAp);
    cudaGetSymbolAddress((void**)&psB,  g_sB);

    const dim3 encGrid(DEMB / 128, MTOT / 128);   // (4, 288)

    gemm_enc<false><<<encGrid, 256>>>(pep_esm, rec_esm, pep_pw, rec_pw,
                                      pep_pb, rec_pb, pE, DIN);
    gemm_enc<true ><<<encGrid, 256>>>(pE, pE + (size_t)MPEP * DEMB,
                                      pep_f1w, rec_f1w, pep_f1b, rec_f1b, pH, DEMB);
    ln_merged<<<MTOT, 256>>>(pH, pep_lng, pep_lnb, rec_lng, rec_lnb);
    gemm_enc<false><<<encGrid, 256>>>(pH, pH + (size_t)MPEP * DEMB,
                                      pep_f2w, rec_f2w, pep_f2b, rec_f2b, pE, DEMB);
    rownorm_merged<<<MTOT, 256>>>(pE, phAb, phBb);

    sim_bf<<<dim3(TB / 128, BB, BB), 256>>>(phAb, phBb, pep_mask, rec_mask, temp, psAp, psB);

    finalize_kernel<<<dim3(BB, BB), 256>>>(psAp, psB, pep_mask, rec_mask, (float*)d_out);
}